// round 3
// baseline (speedup 1.0000x reference)
#include <cuda_runtime.h>
#include <math.h>
#include <stdint.h>

#define NN 50000
#define EE 800000
#define E2 (EE + NN)
#define BN_EPS 1e-5f

// ---------------- scratch (static __device__, no allocations) ----------------
__device__ int   g_is64;
__device__ int   g_src[EE];
__device__ int   g_dst[EE];
__device__ int   g_deg[NN];
__device__ int   g_rowptr[NN + 1];
__device__ int   g_fill[NN];
__device__ int   g_colsrc[E2];
__device__ float g_dinv[NN];
__device__ float g_bufA[NN * 64];
__device__ float g_bufB[NN * 64];
__device__ float g_hbuf[(size_t)NN * 512];   // 102.4 MB: GAT transformed features
__device__ float g_es[NN * 8];
__device__ float g_ed[NN * 8];

// ---------------- helpers ----------------
__device__ __forceinline__ float warp_max(float v) {
    #pragma unroll
    for (int o = 16; o; o >>= 1) v = fmaxf(v, __shfl_xor_sync(0xffffffffu, v, o));
    return v;
}
__device__ __forceinline__ float warp_sum(float v) {
    #pragma unroll
    for (int o = 16; o; o >>= 1) v += __shfl_xor_sync(0xffffffffu, v, o);
    return v;
}
__device__ __forceinline__ float lrelu(float x) { return x > 0.f ? x : 0.2f * x; }

// ---------------- graph-structure kernels ----------------

// Detect whether edge_index is int64 (odd 32-bit words all zero) or int32.
// One warp samples 1024 odd words.
__global__ void detect_kernel(const int* __restrict__ ei) {
    int l = threadIdx.x;           // 32 lanes
    int any = 0;
    #pragma unroll
    for (int j = 0; j < 32; j++) {
        int i = j * 32 + l;
        any |= ei[2 * i + 1];
    }
    #pragma unroll
    for (int o = 16; o; o >>= 1) any |= __shfl_xor_sync(0xffffffffu, any, o);
    if (l == 0) g_is64 = (any == 0) ? 1 : 0;
}

// Convert edge list to int32, and init deg[i]=1 (self-loop) for i<NN.
__global__ void convert_kernel(const void* __restrict__ ei) {
    int e = blockIdx.x * blockDim.x + threadIdx.x;
    if (e < NN) g_deg[e] = 1;
    if (e >= EE) return;
    if (g_is64) {
        const long long* p = (const long long*)ei;
        g_src[e] = (int)p[e];
        g_dst[e] = (int)p[EE + e];
    } else {
        const int* p = (const int*)ei;
        g_src[e] = p[e];
        g_dst[e] = p[EE + e];
    }
}

__global__ void count_kernel() {
    int e = blockIdx.x * blockDim.x + threadIdx.x;
    if (e >= EE) return;
    atomicAdd(&g_deg[g_dst[e]], 1);
}

// Exclusive scan of deg -> rowptr, plus dinv and fill init. Single block.
__global__ void scan_kernel() {
    __shared__ int sh[1024];
    const int CH = (NN + 1023) / 1024;
    int t = threadIdx.x;
    int b = t * CH;
    int e = min(b + CH, NN);
    int s = 0;
    for (int i = b; i < e; i++) s += g_deg[i];
    sh[t] = s;
    __syncthreads();
    for (int off = 1; off < 1024; off <<= 1) {
        int v = (t >= off) ? sh[t - off] : 0;
        __syncthreads();
        sh[t] += v;
        __syncthreads();
    }
    int base = (t == 0) ? 0 : sh[t - 1];
    for (int i = b; i < e; i++) {
        g_rowptr[i] = base;
        g_fill[i]   = base;
        g_dinv[i]   = rsqrtf((float)g_deg[i]);
        base += g_deg[i];
    }
    if (t == 1023) g_rowptr[NN] = sh[1023];
}

__global__ void fill_kernel() {
    int idx = blockIdx.x * blockDim.x + threadIdx.x;
    if (idx >= E2) return;
    int s, d;
    if (idx < EE) { s = g_src[idx]; d = g_dst[idx]; }
    else          { s = d = idx - EE; }
    int pos = atomicAdd(&g_fill[d], 1);
    g_colsrc[pos] = s;
}

// Insertion-sort each row by src -> deterministic fp accumulation order.
__global__ void sort_kernel() {
    int r = blockIdx.x * blockDim.x + threadIdx.x;
    if (r >= NN) return;
    int s0 = g_rowptr[r], s1 = g_rowptr[r + 1];
    for (int i = s0 + 1; i < s1; i++) {
        int v = g_colsrc[i];
        int j = i - 1;
        while (j >= s0 && g_colsrc[j] > v) { g_colsrc[j + 1] = g_colsrc[j]; j--; }
        g_colsrc[j + 1] = v;
    }
}

// ---------------- dense GEMM: Y[M,NO] = X[M,K] @ W[K,NO] ----------------
// 32 rows x 64 cols per block; 256 threads; W tile staged in shared.
template <int K, int NO>
__global__ __launch_bounds__(256) void gemm_kernel(const float* __restrict__ X,
                                                   const float* __restrict__ W,
                                                   float* __restrict__ Y) {
    __shared__ float ws[K * 64];
    int colBase = blockIdx.y * 64;
    int rowBase = blockIdx.x * 32;
    int t = threadIdx.x;
    for (int idx = t; idx < K * 64; idx += 256) {
        int k = idx >> 6, c = idx & 63;
        ws[idx] = W[k * NO + colBase + c];
    }
    __syncthreads();
    int row = rowBase + (t >> 3);
    int cg  = (t & 7) * 8;
    if (row >= NN) return;
    float acc[8];
    #pragma unroll
    for (int j = 0; j < 8; j++) acc[j] = 0.f;
    const float4* x4 = (const float4*)(X + (size_t)row * K);
    #pragma unroll 4
    for (int k4 = 0; k4 < K / 4; k4++) {
        float4 a = x4[k4];
        int kb = k4 * 4;
        #pragma unroll
        for (int j = 0; j < 8; j++) {
            acc[j] += a.x * ws[(kb + 0) * 64 + cg + j];
            acc[j] += a.y * ws[(kb + 1) * 64 + cg + j];
            acc[j] += a.z * ws[(kb + 2) * 64 + cg + j];
            acc[j] += a.w * ws[(kb + 3) * 64 + cg + j];
        }
    }
    float* yr = Y + (size_t)row * NO + colBase + cg;
    ((float4*)yr)[0] = make_float4(acc[0], acc[1], acc[2], acc[3]);
    ((float4*)yr)[1] = make_float4(acc[4], acc[5], acc[6], acc[7]);
}

// ---------------- GCN aggregation + bias + BN(eval) + ReLU ----------------
// one warp per dst node; lane handles channels l and l+32
__global__ __launch_bounds__(256) void gcn_agg_kernel(const float* __restrict__ h,
                                                      const float* __restrict__ bias,
                                                      const float* __restrict__ gamma,
                                                      const float* __restrict__ beta,
                                                      const float* __restrict__ mean,
                                                      const float* __restrict__ var,
                                                      float* __restrict__ out) {
    int w = (blockIdx.x * blockDim.x + threadIdx.x) >> 5;
    int l = threadIdx.x & 31;
    if (w >= NN) return;
    int s0 = g_rowptr[w], s1 = g_rowptr[w + 1];
    float a0 = 0.f, a1 = 0.f;
    for (int i = s0; i < s1; i++) {
        int s = g_colsrc[i];
        float dv = g_dinv[s];
        const float* hp = h + (size_t)s * 64;
        a0 += dv * hp[l];
        a1 += dv * hp[l + 32];
    }
    float dd = g_dinv[w];
    float v0 = a0 * dd + bias[l];
    float v1 = a1 * dd + bias[l + 32];
    v0 = (v0 - mean[l])      * rsqrtf(var[l]      + BN_EPS) * gamma[l]      + beta[l];
    v1 = (v1 - mean[l + 32]) * rsqrtf(var[l + 32] + BN_EPS) * gamma[l + 32] + beta[l + 32];
    v0 = fmaxf(v0, 0.f);
    v1 = fmaxf(v1, 0.f);
    out[(size_t)w * 64 + l]      = v0;
    out[(size_t)w * 64 + l + 32] = v1;
}

// ---------------- GAT per-node attention coefficients ----------------
// one warp per (node, head): es = <h_nh, asrc_h>, ed = <h_nh, adst_h>
template <int CH>
__global__ __launch_bounds__(256) void esed_kernel(const float* __restrict__ hb,
                                                   const float* __restrict__ asrc,
                                                   const float* __restrict__ adst,
                                                   float* __restrict__ es,
                                                   float* __restrict__ ed) {
    int wid = (blockIdx.x * blockDim.x + threadIdx.x) >> 5;
    int l   = threadIdx.x & 31;
    if (wid >= NN * 8) return;
    int n = wid >> 3, hh = wid & 7;
    const float* hp = hb + (size_t)n * (8 * CH) + hh * CH;
    const float* as = asrc + hh * CH;
    const float* ad = adst + hh * CH;
    float s, d;
    if (CH == 64) {
        float v0 = hp[l], v1 = hp[l + 32];
        s = v0 * as[l] + v1 * as[l + 32];
        d = v0 * ad[l] + v1 * ad[l + 32];
    } else {
        float v0 = hp[l];
        s = v0 * as[l];
        d = v0 * ad[l];
    }
    s = warp_sum(s);
    d = warp_sum(d);
    if (l == 0) { es[n * 8 + hh] = s; ed[n * 8 + hh] = d; }
}

// ---------------- GAT aggregation (softmax over in-edges, mean over heads) ---
// one warp per dst. CH=64: lane owns channels l,l+32; CH=32: lane owns channel l.
template <int CH, int RELU, int LOGSM>
__global__ __launch_bounds__(256) void gat_agg_kernel(const float* __restrict__ hb,
                                                      const float* __restrict__ es,
                                                      const float* __restrict__ ed,
                                                      const float* __restrict__ bias,
                                                      float* __restrict__ out) {
    int d = (blockIdx.x * blockDim.x + threadIdx.x) >> 5;
    int l = threadIdx.x & 31;
    if (d >= NN) return;
    int s0 = g_rowptr[d], s1 = g_rowptr[d + 1];

    float edv[8];
    {
        const float4* e4 = (const float4*)(ed + d * 8);
        float4 a = e4[0], b = e4[1];
        edv[0] = a.x; edv[1] = a.y; edv[2] = a.z; edv[3] = a.w;
        edv[4] = b.x; edv[5] = b.y; edv[6] = b.z; edv[7] = b.w;
    }

    // pass 1: per-head max (lane-strided over edges; max is order-independent)
    float m[8];
    #pragma unroll
    for (int h = 0; h < 8; h++) m[h] = -1e30f;
    for (int i = s0 + l; i < s1; i += 32) {
        int s = g_colsrc[i];
        const float4* e4 = (const float4*)(es + s * 8);
        float4 a = e4[0], b = e4[1];
        float ev[8] = {a.x, a.y, a.z, a.w, b.x, b.y, b.z, b.w};
        #pragma unroll
        for (int h = 0; h < 8; h++) m[h] = fmaxf(m[h], lrelu(ev[h] + edv[h]));
    }
    #pragma unroll
    for (int h = 0; h < 8; h++) m[h] = warp_max(m[h]);

    // pass 2: per-head denom (fixed lane-strided order -> deterministic)
    float den[8];
    #pragma unroll
    for (int h = 0; h < 8; h++) den[h] = 0.f;
    for (int i = s0 + l; i < s1; i += 32) {
        int s = g_colsrc[i];
        const float4* e4 = (const float4*)(es + s * 8);
        float4 a = e4[0], b = e4[1];
        float ev[8] = {a.x, a.y, a.z, a.w, b.x, b.y, b.z, b.w};
        #pragma unroll
        for (int h = 0; h < 8; h++) den[h] += expf(lrelu(ev[h] + edv[h]) - m[h]);
    }
    float rden[8];
    #pragma unroll
    for (int h = 0; h < 8; h++) {
        den[h]  = warp_sum(den[h]);
        rden[h] = 1.f / (den[h] + 1e-16f);
    }

    // pass 3: weighted feature sum. All lanes walk edges together;
    // lanes 0..7 compute alpha for head==lane, shuffle-broadcast to all.
    float acc0 = 0.f, acc1 = 0.f;
    for (int i = s0; i < s1; i++) {
        int s = g_colsrc[i];
        float aa = 0.f;
        if (l < 8) {
            float e = lrelu(es[s * 8 + l] + edv[l]);
            aa = expf(e - m[l]) * rden[l];
        }
        const float* hp = hb + (size_t)s * (8 * CH);
        #pragma unroll
        for (int h = 0; h < 8; h++) {
            float al = __shfl_sync(0xffffffffu, aa, h);
            acc0 += al * hp[h * CH + l];
            if (CH == 64) acc1 += al * hp[h * CH + 32 + l];
        }
    }

    float v0 = acc0 * 0.125f + bias[l];
    if (CH == 64) {
        float v1 = acc1 * 0.125f + bias[l + 32];
        if (RELU) { v0 = fmaxf(v0, 0.f); v1 = fmaxf(v1, 0.f); }
        out[(size_t)d * 64 + l]      = v0;
        out[(size_t)d * 64 + l + 32] = v1;
    } else {
        if (RELU) v0 = fmaxf(v0, 0.f);
        if (LOGSM) {
            float mx = warp_max(v0);
            float se = warp_sum(expf(v0 - mx));
            v0 = v0 - mx - logf(se);
        }
        out[(size_t)d * 32 + l] = v0;
    }
}

// ---------------- launch ----------------
extern "C" void kernel_launch(void* const* d_in, const int* in_sizes, int n_in,
                              void* d_out, int out_size) {
    const float* X        = (const float*)d_in[0];
    const void*  EI       = d_in[1];
    const float* gcn1_w   = (const float*)d_in[2];
    const float* gcn1_b   = (const float*)d_in[3];
    const float* bn1_g    = (const float*)d_in[4];
    const float* bn1_be   = (const float*)d_in[5];
    const float* bn1_m    = (const float*)d_in[6];
    const float* bn1_v    = (const float*)d_in[7];
    const float* gat1_w   = (const float*)d_in[8];
    const float* gat1_as  = (const float*)d_in[9];
    const float* gat1_ad  = (const float*)d_in[10];
    const float* gat1_b   = (const float*)d_in[11];
    const float* gcn2_w   = (const float*)d_in[12];
    const float* gcn2_b   = (const float*)d_in[13];
    const float* bn2_g    = (const float*)d_in[14];
    const float* bn2_be   = (const float*)d_in[15];
    const float* bn2_m    = (const float*)d_in[16];
    const float* bn2_v    = (const float*)d_in[17];
    const float* gat2_w   = (const float*)d_in[18];
    const float* gat2_as  = (const float*)d_in[19];
    const float* gat2_ad  = (const float*)d_in[20];
    const float* gat2_b   = (const float*)d_in[21];
    float* OUT = (float*)d_out;

    float *bufA, *bufB, *hbuf, *es, *ed;
    cudaGetSymbolAddress((void**)&bufA, g_bufA);
    cudaGetSymbolAddress((void**)&bufB, g_bufB);
    cudaGetSymbolAddress((void**)&hbuf, g_hbuf);
    cudaGetSymbolAddress((void**)&es,   g_es);
    cudaGetSymbolAddress((void**)&ed,   g_ed);

    const int TB = 256;
    // graph structure (per-launch, deterministic)
    detect_kernel<<<1, 32>>>((const int*)EI);
    convert_kernel<<<(EE + TB - 1) / TB, TB>>>(EI);
    count_kernel<<<(EE + TB - 1) / TB, TB>>>();
    scan_kernel<<<1, 1024>>>();
    fill_kernel<<<(E2 + TB - 1) / TB, TB>>>();
    sort_kernel<<<(NN + TB - 1) / TB, TB>>>();

    dim3 gRows((NN + 31) / 32, 1);
    int  aggBlocks  = (NN * 32 + TB - 1) / TB;
    int  esedBlocks = (NN * 8 * 32 + TB - 1) / TB;

    // layer 1: GCN -> BN -> ReLU
    gemm_kernel<128, 64><<<dim3(gRows.x, 1), TB>>>(X, gcn1_w, bufA);
    gcn_agg_kernel<<<aggBlocks, TB>>>(bufA, gcn1_b, bn1_g, bn1_be, bn1_m, bn1_v, bufB);

    // layer 2: GAT(8 heads, 64 ch, mean) -> ReLU
    gemm_kernel<64, 512><<<dim3(gRows.x, 8), TB>>>(bufB, gat1_w, hbuf);
    esed_kernel<64><<<esedBlocks, TB>>>(hbuf, gat1_as, gat1_ad, es, ed);
    gat_agg_kernel<64, 1, 0><<<aggBlocks, TB>>>(hbuf, es, ed, gat1_b, bufA);

    // layer 3: GCN -> BN -> ReLU
    gemm_kernel<64, 64><<<dim3(gRows.x, 1), TB>>>(bufA, gcn2_w, bufB);
    gcn_agg_kernel<<<aggBlocks, TB>>>(bufB, gcn2_b, bn2_g, bn2_be, bn2_m, bn2_v, bufA);

    // layer 4: GAT(8 heads, 32 ch, mean) + log_softmax
    gemm_kernel<64, 256><<<dim3(gRows.x, 4), TB>>>(bufA, gat2_w, hbuf);
    esed_kernel<32><<<esedBlocks, TB>>>(hbuf, gat2_as, gat2_ad, es, ed);
    gat_agg_kernel<32, 0, 1><<<aggBlocks, TB>>>(hbuf, es, ed, gat2_b, OUT);
}

// round 4
// speedup vs baseline: 1.1990x; 1.1990x over previous
#include <cuda_runtime.h>
#include <cuda_fp16.h>
#include <math.h>
#include <stdint.h>

#define NN 50000
#define EE 800000
#define E2 (EE + NN)
#define NB ((NN + 255) / 256)     // 196 blocks for node-scan
#define BN_EPS 1e-5f

// ---------------- scratch (static __device__, no allocations) ----------------
__device__ int    g_is64;
__device__ int    g_src[EE];
__device__ int    g_dst[EE];
__device__ int    g_deg[NN];          // WITHOUT self-loop (memset 0, atomics)
__device__ int    g_bsum[256];
__device__ int    g_boff[256];
__device__ int    g_rowptr[NN + 1];
__device__ int    g_fill[NN];
__device__ int    g_colsrc[E2];
__device__ float  g_dinv[NN];
__device__ float  g_bufA[NN * 64];
__device__ float  g_bufB[NN * 64];
__device__ __half g_hbuf[(size_t)NN * 512];   // 51.2 MB: GAT features (fp16)
__device__ float  g_es[NN * 8];
__device__ float  g_ed[NN * 8];

// ---------------- helpers ----------------
__device__ __forceinline__ float warp_max(float v) {
    #pragma unroll
    for (int o = 16; o; o >>= 1) v = fmaxf(v, __shfl_xor_sync(0xffffffffu, v, o));
    return v;
}
__device__ __forceinline__ float warp_sum(float v) {
    #pragma unroll
    for (int o = 16; o; o >>= 1) v += __shfl_xor_sync(0xffffffffu, v, o);
    return v;
}
__device__ __forceinline__ float lrelu(float x) { return x > 0.f ? x : 0.2f * x; }

// ---------------- graph-structure kernels ----------------

// Detect whether edge_index is int64 (odd 32-bit words all zero) or int32.
__global__ void detect_kernel(const int* __restrict__ ei) {
    int l = threadIdx.x;
    int any = 0;
    #pragma unroll
    for (int j = 0; j < 32; j++) any |= ei[2 * (j * 32 + l) + 1];
    #pragma unroll
    for (int o = 16; o; o >>= 1) any |= __shfl_xor_sync(0xffffffffu, any, o);
    if (l == 0) g_is64 = (any == 0) ? 1 : 0;
}

// Convert edge list to int32 AND count in-degree (deg pre-zeroed by memset).
__global__ void convert_count_kernel(const void* __restrict__ ei) {
    int e = blockIdx.x * blockDim.x + threadIdx.x;
    if (e >= EE) return;
    int s, d;
    if (g_is64) {
        const long long* p = (const long long*)ei;
        s = (int)p[e];
        d = (int)p[EE + e];
    } else {
        const int* p = (const int*)ei;
        s = p[e];
        d = p[EE + e];
    }
    g_src[e] = s;
    g_dst[e] = d;
    atomicAdd(&g_deg[d], 1);
}

// Phase 1: per-block sums of (deg+1).
__global__ __launch_bounds__(256) void bsum_kernel() {
    __shared__ int sh[256];
    int t = threadIdx.x;
    int n = blockIdx.x * 256 + t;
    int v = (n < NN) ? (g_deg[n] + 1) : 0;
    sh[t] = v;
    __syncthreads();
    #pragma unroll
    for (int o = 128; o; o >>= 1) {
        if (t < o) sh[t] += sh[t + o];
        __syncthreads();
    }
    if (t == 0) g_bsum[blockIdx.x] = sh[0];
}

// Phase 2: exclusive scan of the 196 block sums (single small block).
__global__ __launch_bounds__(256) void bscan_kernel() {
    __shared__ int sh[256];
    int t = threadIdx.x;
    int v = (t < NB) ? g_bsum[t] : 0;
    sh[t] = v;
    __syncthreads();
    #pragma unroll
    for (int o = 1; o < 256; o <<= 1) {
        int u = (t >= o) ? sh[t - o] : 0;
        __syncthreads();
        sh[t] += u;
        __syncthreads();
    }
    g_boff[t] = sh[t] - v;   // exclusive
}

// Phase 3: per-block exclusive scan + global offset -> rowptr/fill/dinv.
__global__ __launch_bounds__(256) void rowptr_kernel() {
    __shared__ int sh[256];
    int t = threadIdx.x;
    int n = blockIdx.x * 256 + t;
    int v = (n < NN) ? (g_deg[n] + 1) : 0;
    sh[t] = v;
    __syncthreads();
    #pragma unroll
    for (int o = 1; o < 256; o <<= 1) {
        int u = (t >= o) ? sh[t - o] : 0;
        __syncthreads();
        sh[t] += u;
        __syncthreads();
    }
    int excl = sh[t] - v + g_boff[blockIdx.x];
    if (n < NN) {
        g_rowptr[n] = excl;
        g_fill[n]   = excl;
        g_dinv[n]   = rsqrtf((float)v);
    }
    if (n == NN - 1) g_rowptr[NN] = excl + v;
}

__global__ void fill_kernel() {
    int idx = blockIdx.x * blockDim.x + threadIdx.x;
    if (idx >= E2) return;
    int s, d;
    if (idx < EE) { s = g_src[idx]; d = g_dst[idx]; }
    else          { s = d = idx - EE; }
    int pos = atomicAdd(&g_fill[d], 1);
    g_colsrc[pos] = s;
}

// Insertion-sort each row by src -> deterministic fp accumulation order.
__global__ void sort_kernel() {
    int r = blockIdx.x * blockDim.x + threadIdx.x;
    if (r >= NN) return;
    int s0 = g_rowptr[r], s1 = g_rowptr[r + 1];
    for (int i = s0 + 1; i < s1; i++) {
        int v = g_colsrc[i];
        int j = i - 1;
        while (j >= s0 && g_colsrc[j] > v) { g_colsrc[j + 1] = g_colsrc[j]; j--; }
        g_colsrc[j + 1] = v;
    }
}

// ---------------- dense GEMM (fp32 out): Y[M,NO] = X[M,K] @ W[K,NO] ---------
template <int K, int NO>
__global__ __launch_bounds__(256) void gemm_kernel(const float* __restrict__ X,
                                                   const float* __restrict__ W,
                                                   float* __restrict__ Y) {
    __shared__ float ws[K * 64];
    int colBase = blockIdx.y * 64;
    int rowBase = blockIdx.x * 32;
    int t = threadIdx.x;
    for (int idx = t; idx < K * 64; idx += 256) {
        int k = idx >> 6, c = idx & 63;
        ws[idx] = W[k * NO + colBase + c];
    }
    __syncthreads();
    int row = rowBase + (t >> 3);
    int cg  = (t & 7) * 8;
    if (row >= NN) return;
    float acc[8];
    #pragma unroll
    for (int j = 0; j < 8; j++) acc[j] = 0.f;
    const float4* x4 = (const float4*)(X + (size_t)row * K);
    #pragma unroll 4
    for (int k4 = 0; k4 < K / 4; k4++) {
        float4 a = x4[k4];
        int kb = k4 * 4;
        #pragma unroll
        for (int j = 0; j < 8; j++) {
            acc[j] += a.x * ws[(kb + 0) * 64 + cg + j];
            acc[j] += a.y * ws[(kb + 1) * 64 + cg + j];
            acc[j] += a.z * ws[(kb + 2) * 64 + cg + j];
            acc[j] += a.w * ws[(kb + 3) * 64 + cg + j];
        }
    }
    float* yr = Y + (size_t)row * NO + colBase + cg;
    ((float4*)yr)[0] = make_float4(acc[0], acc[1], acc[2], acc[3]);
    ((float4*)yr)[1] = make_float4(acc[4], acc[5], acc[6], acc[7]);
}

// ------- GAT GEMM (fp16 out) + fused es/ed epilogue -------
// Each block's 64-col tile covers whole heads (CH=64: 1 head; CH=32: 2 heads).
// es[n,h] = <h_nh, asrc_h>, ed likewise — reduced across the 8 lanes of a row
// (width 8 for CH=64, width 4 for CH=32) from the fp32 accumulators.
template <int K, int NO, int CH>
__global__ __launch_bounds__(256) void gemm_gat_kernel(const float* __restrict__ X,
                                                       const float* __restrict__ W,
                                                       const float* __restrict__ asrc,
                                                       const float* __restrict__ adst,
                                                       __half* __restrict__ Y,
                                                       float* __restrict__ es,
                                                       float* __restrict__ ed) {
    __shared__ float ws[K * 64];
    int colBase = blockIdx.y * 64;
    int rowBase = blockIdx.x * 32;
    int t = threadIdx.x;
    for (int idx = t; idx < K * 64; idx += 256) {
        int k = idx >> 6, c = idx & 63;
        ws[idx] = W[k * NO + colBase + c];
    }
    __syncthreads();
    int row = rowBase + (t >> 3);
    int cg  = (t & 7) * 8;
    if (row >= NN) return;   // NN%4==0 -> whole warps exit together
    float acc[8];
    #pragma unroll
    for (int j = 0; j < 8; j++) acc[j] = 0.f;
    const float4* x4 = (const float4*)(X + (size_t)row * K);
    #pragma unroll 4
    for (int k4 = 0; k4 < K / 4; k4++) {
        float4 a = x4[k4];
        int kb = k4 * 4;
        #pragma unroll
        for (int j = 0; j < 8; j++) {
            acc[j] += a.x * ws[(kb + 0) * 64 + cg + j];
            acc[j] += a.y * ws[(kb + 1) * 64 + cg + j];
            acc[j] += a.z * ws[(kb + 2) * 64 + cg + j];
            acc[j] += a.w * ws[(kb + 3) * 64 + cg + j];
        }
    }
    // store fp16
    __half* yr = Y + (size_t)row * NO + colBase + cg;
    #pragma unroll
    for (int j = 0; j < 8; j += 2)
        ((__half2*)yr)[j >> 1] = __floats2half2_rn(acc[j], acc[j + 1]);

    // fused es/ed epilogue
    int col  = colBase + cg;
    int head = col / CH;
    int cwh  = col % CH;
    float ds = 0.f, dd = 0.f;
    #pragma unroll
    for (int j = 0; j < 8; j++) {
        ds += acc[j] * asrc[head * CH + cwh + j];
        dd += acc[j] * adst[head * CH + cwh + j];
    }
    const int RW = (CH == 64) ? 8 : 4;
    #pragma unroll
    for (int o = RW / 2; o; o >>= 1) {
        ds += __shfl_down_sync(0xffffffffu, ds, o, RW);
        dd += __shfl_down_sync(0xffffffffu, dd, o, RW);
    }
    if ((t & (RW - 1)) == 0) {
        es[row * 8 + head] = ds;
        ed[row * 8 + head] = dd;
    }
}

// ---------------- GCN aggregation + bias + BN(eval) + ReLU ----------------
__global__ __launch_bounds__(256) void gcn_agg_kernel(const float* __restrict__ h,
                                                      const float* __restrict__ bias,
                                                      const float* __restrict__ gamma,
                                                      const float* __restrict__ beta,
                                                      const float* __restrict__ mean,
                                                      const float* __restrict__ var,
                                                      float* __restrict__ out) {
    int w = (blockIdx.x * blockDim.x + threadIdx.x) >> 5;
    int l = threadIdx.x & 31;
    if (w >= NN) return;
    int s0 = g_rowptr[w], s1 = g_rowptr[w + 1];
    float a0 = 0.f, a1 = 0.f;
    for (int i = s0; i < s1; i++) {
        int s = g_colsrc[i];
        float dv = g_dinv[s];
        const float* hp = h + (size_t)s * 64;
        a0 += dv * hp[l];
        a1 += dv * hp[l + 32];
    }
    float dd = g_dinv[w];
    float v0 = a0 * dd + bias[l];
    float v1 = a1 * dd + bias[l + 32];
    v0 = (v0 - mean[l])      * rsqrtf(var[l]      + BN_EPS) * gamma[l]      + beta[l];
    v1 = (v1 - mean[l + 32]) * rsqrtf(var[l + 32] + BN_EPS) * gamma[l + 32] + beta[l + 32];
    out[(size_t)w * 64 + l]      = fmaxf(v0, 0.f);
    out[(size_t)w * 64 + l + 32] = fmaxf(v1, 0.f);
}

// ---------------- GAT aggregation (softmax over in-edges, mean over heads) ---
// one warp per dst. CH=64: lane owns channel pair (2l,2l+1) via __half2;
// CH=32: lane owns channel l.
template <int CH, int RELU, int LOGSM>
__global__ __launch_bounds__(256) void gat_agg_kernel(const __half* __restrict__ hb,
                                                      const float* __restrict__ es,
                                                      const float* __restrict__ ed,
                                                      const float* __restrict__ bias,
                                                      float* __restrict__ out) {
    int d = (blockIdx.x * blockDim.x + threadIdx.x) >> 5;
    int l = threadIdx.x & 31;
    if (d >= NN) return;
    int s0 = g_rowptr[d], s1 = g_rowptr[d + 1];

    float edv[8];
    {
        const float4* e4 = (const float4*)(ed + d * 8);
        float4 a = e4[0], b = e4[1];
        edv[0] = a.x; edv[1] = a.y; edv[2] = a.z; edv[3] = a.w;
        edv[4] = b.x; edv[5] = b.y; edv[6] = b.z; edv[7] = b.w;
    }

    // pass 1: per-head max (order-independent)
    float m[8];
    #pragma unroll
    for (int h = 0; h < 8; h++) m[h] = -1e30f;
    for (int i = s0 + l; i < s1; i += 32) {
        int s = g_colsrc[i];
        const float4* e4 = (const float4*)(es + s * 8);
        float4 a = e4[0], b = e4[1];
        float ev[8] = {a.x, a.y, a.z, a.w, b.x, b.y, b.z, b.w};
        #pragma unroll
        for (int h = 0; h < 8; h++) m[h] = fmaxf(m[h], lrelu(ev[h] + edv[h]));
    }
    #pragma unroll
    for (int h = 0; h < 8; h++) m[h] = warp_max(m[h]);

    // pass 2: per-head denom (fixed lane-strided order -> deterministic)
    float den[8];
    #pragma unroll
    for (int h = 0; h < 8; h++) den[h] = 0.f;
    for (int i = s0 + l; i < s1; i += 32) {
        int s = g_colsrc[i];
        const float4* e4 = (const float4*)(es + s * 8);
        float4 a = e4[0], b = e4[1];
        float ev[8] = {a.x, a.y, a.z, a.w, b.x, b.y, b.z, b.w};
        #pragma unroll
        for (int h = 0; h < 8; h++) den[h] += expf(lrelu(ev[h] + edv[h]) - m[h]);
    }
    float rden[8];
    #pragma unroll
    for (int h = 0; h < 8; h++) {
        den[h]  = warp_sum(den[h]);
        rden[h] = 1.f / (den[h] + 1e-16f);
    }

    // pass 3: weighted feature sum. Lanes 0..7 compute alpha for head==lane,
    // shuffle-broadcast to all lanes.
    float acc0 = 0.f, acc1 = 0.f;
    for (int i = s0; i < s1; i++) {
        int s = g_colsrc[i];
        float aa = 0.f;
        if (l < 8) {
            float e = lrelu(es[s * 8 + l] + edv[l]);
            aa = expf(e - m[l]) * rden[l];
        }
        if (CH == 64) {
            const __half2* hp = (const __half2*)(hb + (size_t)s * 512);
            #pragma unroll
            for (int h = 0; h < 8; h++) {
                float al = __shfl_sync(0xffffffffu, aa, h);
                float2 v = __half22float2(hp[h * 32 + l]);
                acc0 += al * v.x;
                acc1 += al * v.y;
            }
        } else {
            const __half* hp = hb + (size_t)s * 256;
            #pragma unroll
            for (int h = 0; h < 8; h++) {
                float al = __shfl_sync(0xffffffffu, aa, h);
                acc0 += al * __half2float(hp[h * 32 + l]);
            }
        }
    }

    if (CH == 64) {
        float v0 = acc0 * 0.125f + bias[2 * l];
        float v1 = acc1 * 0.125f + bias[2 * l + 1];
        if (RELU) { v0 = fmaxf(v0, 0.f); v1 = fmaxf(v1, 0.f); }
        ((float2*)(out + (size_t)d * 64))[l] = make_float2(v0, v1);
    } else {
        float v0 = acc0 * 0.125f + bias[l];
        if (RELU) v0 = fmaxf(v0, 0.f);
        if (LOGSM) {
            float mx = warp_max(v0);
            float se = warp_sum(expf(v0 - mx));
            v0 = v0 - mx - logf(se);
        }
        out[(size_t)d * 32 + l] = v0;
    }
}

// ---------------- launch ----------------
extern "C" void kernel_launch(void* const* d_in, const int* in_sizes, int n_in,
                              void* d_out, int out_size) {
    const float* X        = (const float*)d_in[0];
    const void*  EI       = d_in[1];
    const float* gcn1_w   = (const float*)d_in[2];
    const float* gcn1_b   = (const float*)d_in[3];
    const float* bn1_g    = (const float*)d_in[4];
    const float* bn1_be   = (const float*)d_in[5];
    const float* bn1_m    = (const float*)d_in[6];
    const float* bn1_v    = (const float*)d_in[7];
    const float* gat1_w   = (const float*)d_in[8];
    const float* gat1_as  = (const float*)d_in[9];
    const float* gat1_ad  = (const float*)d_in[10];
    const float* gat1_b   = (const float*)d_in[11];
    const float* gcn2_w   = (const float*)d_in[12];
    const float* gcn2_b   = (const float*)d_in[13];
    const float* bn2_g    = (const float*)d_in[14];
    const float* bn2_be   = (const float*)d_in[15];
    const float* bn2_m    = (const float*)d_in[16];
    const float* bn2_v    = (const float*)d_in[17];
    const float* gat2_w   = (const float*)d_in[18];
    const float* gat2_as  = (const float*)d_in[19];
    const float* gat2_ad  = (const float*)d_in[20];
    const float* gat2_b   = (const float*)d_in[21];
    float* OUT = (float*)d_out;

    float *bufA, *bufB, *es, *ed;
    __half* hbuf;
    int* degPtr;
    cudaGetSymbolAddress((void**)&bufA,   g_bufA);
    cudaGetSymbolAddress((void**)&bufB,   g_bufB);
    cudaGetSymbolAddress((void**)&hbuf,   g_hbuf);
    cudaGetSymbolAddress((void**)&es,     g_es);
    cudaGetSymbolAddress((void**)&ed,     g_ed);
    cudaGetSymbolAddress((void**)&degPtr, g_deg);

    const int TB = 256;
    // graph structure (per-launch, deterministic)
    detect_kernel<<<1, 32>>>((const int*)EI);
    cudaMemsetAsync(degPtr, 0, NN * sizeof(int));
    convert_count_kernel<<<(EE + TB - 1) / TB, TB>>>(EI);
    bsum_kernel<<<NB, 256>>>();
    bscan_kernel<<<1, 256>>>();
    rowptr_kernel<<<NB, 256>>>();
    fill_kernel<<<(E2 + TB - 1) / TB, TB>>>();
    sort_kernel<<<(NN + TB - 1) / TB, TB>>>();

    int gRows     = (NN + 31) / 32;
    int aggBlocks = (NN * 32 + TB - 1) / TB;

    // layer 1: GCN -> BN -> ReLU
    gemm_kernel<128, 64><<<dim3(gRows, 1), TB>>>(X, gcn1_w, bufA);
    gcn_agg_kernel<<<aggBlocks, TB>>>(bufA, gcn1_b, bn1_g, bn1_be, bn1_m, bn1_v, bufB);

    // layer 2: GAT(8 heads, 64 ch, mean) -> ReLU  [es/ed fused into GEMM]
    gemm_gat_kernel<64, 512, 64><<<dim3(gRows, 8), TB>>>(bufB, gat1_w, gat1_as, gat1_ad, hbuf, es, ed);
    gat_agg_kernel<64, 1, 0><<<aggBlocks, TB>>>(hbuf, es, ed, gat1_b, bufA);

    // layer 3: GCN -> BN -> ReLU
    gemm_kernel<64, 64><<<dim3(gRows, 1), TB>>>(bufA, gcn2_w, bufB);
    gcn_agg_kernel<<<aggBlocks, TB>>>(bufB, gcn2_b, bn2_g, bn2_be, bn2_m, bn2_v, bufA);

    // layer 4: GAT(8 heads, 32 ch, mean) + log_softmax
    gemm_gat_kernel<64, 256, 32><<<dim3(gRows, 4), TB>>>(bufA, gat2_w, gat2_as, gat2_ad, hbuf, es, ed);
    gat_agg_kernel<32, 0, 1><<<aggBlocks, TB>>>(hbuf, es, ed, gat2_b, OUT);
}

// round 5
// speedup vs baseline: 1.5711x; 1.3103x over previous
#include <cuda_runtime.h>
#include <cuda_fp16.h>
#include <math.h>
#include <stdint.h>

#define NN 50000
#define EE 800000
#define E2 (EE + NN)
#define NB ((NN + 255) / 256)
#define BN_EPS 1e-5f

// ---------------- scratch (static __device__, no allocations) ----------------
__device__ int    g_is64;
__device__ int    g_src[EE];
__device__ int    g_dst[EE];
__device__ int    g_deg[NN];
__device__ int    g_bsum[256];
__device__ int    g_boff[256];
__device__ int    g_rowptr[NN + 1];
__device__ int    g_fill[NN];
__device__ int    g_colsrc[E2];
__device__ float  g_dinv[NN];
__device__ float  g_bufA[NN * 64];
__device__ float  g_bufB[NN * 64];
__device__ __half g_hbuf[(size_t)NN * 512];   // 51.2 MB fp16 feature buffer
__device__ float  g_es[NN * 8];
__device__ float  g_ed[NN * 8];

// ---------------- helpers ----------------
__device__ __forceinline__ float warp_max(float v) {
    #pragma unroll
    for (int o = 16; o; o >>= 1) v = fmaxf(v, __shfl_xor_sync(0xffffffffu, v, o));
    return v;
}
__device__ __forceinline__ float warp_sum(float v) {
    #pragma unroll
    for (int o = 16; o; o >>= 1) v += __shfl_xor_sync(0xffffffffu, v, o);
    return v;
}
__device__ __forceinline__ float lrelu(float x) { return x > 0.f ? x : 0.2f * x; }

// ---------------- graph-structure kernels ----------------
__global__ void detect_kernel(const int* __restrict__ ei) {
    int l = threadIdx.x;
    int any = 0;
    #pragma unroll
    for (int j = 0; j < 32; j++) any |= ei[2 * (j * 32 + l) + 1];
    #pragma unroll
    for (int o = 16; o; o >>= 1) any |= __shfl_xor_sync(0xffffffffu, any, o);
    if (l == 0) g_is64 = (any == 0) ? 1 : 0;
}

__global__ void convert_count_kernel(const void* __restrict__ ei) {
    int e = blockIdx.x * blockDim.x + threadIdx.x;
    if (e >= EE) return;
    int s, d;
    if (g_is64) {
        const long long* p = (const long long*)ei;
        s = (int)p[e];
        d = (int)p[EE + e];
    } else {
        const int* p = (const int*)ei;
        s = p[e];
        d = p[EE + e];
    }
    g_src[e] = s;
    g_dst[e] = d;
    atomicAdd(&g_deg[d], 1);
}

__global__ __launch_bounds__(256) void bsum_kernel() {
    __shared__ int sh[256];
    int t = threadIdx.x;
    int n = blockIdx.x * 256 + t;
    int v = (n < NN) ? (g_deg[n] + 1) : 0;
    sh[t] = v;
    __syncthreads();
    #pragma unroll
    for (int o = 128; o; o >>= 1) {
        if (t < o) sh[t] += sh[t + o];
        __syncthreads();
    }
    if (t == 0) g_bsum[blockIdx.x] = sh[0];
}

__global__ __launch_bounds__(256) void bscan_kernel() {
    __shared__ int sh[256];
    int t = threadIdx.x;
    int v = (t < NB) ? g_bsum[t] : 0;
    sh[t] = v;
    __syncthreads();
    #pragma unroll
    for (int o = 1; o < 256; o <<= 1) {
        int u = (t >= o) ? sh[t - o] : 0;
        __syncthreads();
        sh[t] += u;
        __syncthreads();
    }
    g_boff[t] = sh[t] - v;
}

__global__ __launch_bounds__(256) void rowptr_kernel() {
    __shared__ int sh[256];
    int t = threadIdx.x;
    int n = blockIdx.x * 256 + t;
    int v = (n < NN) ? (g_deg[n] + 1) : 0;
    sh[t] = v;
    __syncthreads();
    #pragma unroll
    for (int o = 1; o < 256; o <<= 1) {
        int u = (t >= o) ? sh[t - o] : 0;
        __syncthreads();
        sh[t] += u;
        __syncthreads();
    }
    int excl = sh[t] - v + g_boff[blockIdx.x];
    if (n < NN) {
        g_rowptr[n] = excl;
        g_fill[n]   = excl;
        g_dinv[n]   = rsqrtf((float)v);
    }
    if (n == NN - 1) g_rowptr[NN] = excl + v;
}

__global__ void fill_kernel() {
    int idx = blockIdx.x * blockDim.x + threadIdx.x;
    if (idx >= E2) return;
    int s, d;
    if (idx < EE) { s = g_src[idx]; d = g_dst[idx]; }
    else          { s = d = idx - EE; }
    int pos = atomicAdd(&g_fill[d], 1);
    g_colsrc[pos] = s;
}

__global__ void sort_kernel() {
    int r = blockIdx.x * blockDim.x + threadIdx.x;
    if (r >= NN) return;
    int s0 = g_rowptr[r], s1 = g_rowptr[r + 1];
    for (int i = s0 + 1; i < s1; i++) {
        int v = g_colsrc[i];
        int j = i - 1;
        while (j >= s0 && g_colsrc[j] > v) { g_colsrc[j + 1] = g_colsrc[j]; j--; }
        g_colsrc[j + 1] = v;
    }
}

// ---------------- register-blocked GEMM: Y[M,NO] = X[M,K] @ W[K,NO] ---------
// 128 rows x 64 cols per block; 256 threads; thread computes 8 rows x 4 cols.
// X staged TRANSPOSED in shared (k-major) so 8-row reads vectorize.
template <int K, int NO, bool HALF_OUT>
__global__ __launch_bounds__(256) void gemm_kernel(const float* __restrict__ X,
                                                   const float* __restrict__ W,
                                                   void* __restrict__ Yv) {
    __shared__ float xs[32][128];
    __shared__ float ws[32][64];
    int t = threadIdx.x;
    int tx = t & 15, ty = t >> 4;          // tx: col-group(4), ty: row-group(8)
    int rowBase = blockIdx.x * 128;
    int colBase = blockIdx.y * 64;
    float acc[8][4];
    #pragma unroll
    for (int r = 0; r < 8; r++)
        #pragma unroll
        for (int c = 0; c < 4; c++) acc[r][c] = 0.f;

    for (int kc = 0; kc < K; kc += 32) {
        if (kc) __syncthreads();
        #pragma unroll
        for (int i = 0; i < 8; i++) {
            int idx = i * 256 + t;
            int kk = idx >> 6, c = idx & 63;
            ws[kk][c] = W[(size_t)(kc + kk) * NO + colBase + c];
        }
        #pragma unroll
        for (int i = 0; i < 4; i++) {
            int linear = i * 256 + t;
            int r = linear & 127, c4 = linear >> 7;   // c4 in 0..7
            int row = rowBase + r;
            float4 f = (row < NN)
                ? ((const float4*)(X + (size_t)row * K))[(kc >> 2) + c4]
                : make_float4(0.f, 0.f, 0.f, 0.f);
            xs[c4 * 4 + 0][r] = f.x;
            xs[c4 * 4 + 1][r] = f.y;
            xs[c4 * 4 + 2][r] = f.z;
            xs[c4 * 4 + 3][r] = f.w;
        }
        __syncthreads();
        #pragma unroll 8
        for (int k = 0; k < 32; k++) {
            float4 wv = *(const float4*)&ws[k][tx * 4];
            float4 xa = *(const float4*)&xs[k][ty * 8];
            float4 xb = *(const float4*)&xs[k][ty * 8 + 4];
            float xr[8] = {xa.x, xa.y, xa.z, xa.w, xb.x, xb.y, xb.z, xb.w};
            float wr[4] = {wv.x, wv.y, wv.z, wv.w};
            #pragma unroll
            for (int r = 0; r < 8; r++)
                #pragma unroll
                for (int c = 0; c < 4; c++) acc[r][c] += xr[r] * wr[c];
        }
    }
    #pragma unroll
    for (int r = 0; r < 8; r++) {
        int row = rowBase + ty * 8 + r;
        if (row >= NN) continue;
        if (HALF_OUT) {
            __half2* y = (__half2*)((__half*)Yv + (size_t)row * NO + colBase + tx * 4);
            y[0] = __floats2half2_rn(acc[r][0], acc[r][1]);
            y[1] = __floats2half2_rn(acc[r][2], acc[r][3]);
        } else {
            float4* y = (float4*)((float*)Yv + (size_t)row * NO + colBase + tx * 4);
            *y = make_float4(acc[r][0], acc[r][1], acc[r][2], acc[r][3]);
        }
    }
}

// ------- GAT GEMM (fp16 out) + fused es/ed epilogue -------
// Block's 64 cols cover whole heads (CH=64: 1 head; CH=32: 2 heads).
template <int K, int NO, int CH>
__global__ __launch_bounds__(256) void gemm_gat_kernel(const float* __restrict__ X,
                                                       const float* __restrict__ W,
                                                       const float* __restrict__ asrc,
                                                       const float* __restrict__ adst,
                                                       __half* __restrict__ Y,
                                                       float* __restrict__ es,
                                                       float* __restrict__ ed) {
    __shared__ float xs[32][128];
    __shared__ float ws[32][64];
    int t = threadIdx.x;
    int tx = t & 15, ty = t >> 4;
    int rowBase = blockIdx.x * 128;
    int colBase = blockIdx.y * 64;
    float acc[8][4];
    #pragma unroll
    for (int r = 0; r < 8; r++)
        #pragma unroll
        for (int c = 0; c < 4; c++) acc[r][c] = 0.f;

    for (int kc = 0; kc < K; kc += 32) {
        if (kc) __syncthreads();
        #pragma unroll
        for (int i = 0; i < 8; i++) {
            int idx = i * 256 + t;
            int kk = idx >> 6, c = idx & 63;
            ws[kk][c] = W[(size_t)(kc + kk) * NO + colBase + c];
        }
        #pragma unroll
        for (int i = 0; i < 4; i++) {
            int linear = i * 256 + t;
            int r = linear & 127, c4 = linear >> 7;
            int row = rowBase + r;
            float4 f = (row < NN)
                ? ((const float4*)(X + (size_t)row * K))[(kc >> 2) + c4]
                : make_float4(0.f, 0.f, 0.f, 0.f);
            xs[c4 * 4 + 0][r] = f.x;
            xs[c4 * 4 + 1][r] = f.y;
            xs[c4 * 4 + 2][r] = f.z;
            xs[c4 * 4 + 3][r] = f.w;
        }
        __syncthreads();
        #pragma unroll 8
        for (int k = 0; k < 32; k++) {
            float4 wv = *(const float4*)&ws[k][tx * 4];
            float4 xa = *(const float4*)&xs[k][ty * 8];
            float4 xb = *(const float4*)&xs[k][ty * 8 + 4];
            float xr[8] = {xa.x, xa.y, xa.z, xa.w, xb.x, xb.y, xb.z, xb.w};
            float wr[4] = {wv.x, wv.y, wv.z, wv.w};
            #pragma unroll
            for (int r = 0; r < 8; r++)
                #pragma unroll
                for (int c = 0; c < 4; c++) acc[r][c] += xr[r] * wr[c];
        }
    }
    // fp16 store
    #pragma unroll
    for (int r = 0; r < 8; r++) {
        int row = rowBase + ty * 8 + r;
        if (row >= NN) continue;
        __half2* y = (__half2*)(Y + (size_t)row * NO + colBase + tx * 4);
        y[0] = __floats2half2_rn(acc[r][0], acc[r][1]);
        y[1] = __floats2half2_rn(acc[r][2], acc[r][3]);
    }
    // fused es/ed from fp32 accumulators
    int head = (CH == 64) ? blockIdx.y : (blockIdx.y * 2 + (tx >> 3));
    int cwh  = (CH == 64) ? (tx * 4)   : ((tx & 7) * 4);
    const float* as = asrc + head * CH + cwh;
    const float* ad = adst + head * CH + cwh;
    float a0 = as[0], a1 = as[1], a2 = as[2], a3 = as[3];
    float b0 = ad[0], b1 = ad[1], b2 = ad[2], b3 = ad[3];
    float ds[8], dd[8];
    #pragma unroll
    for (int r = 0; r < 8; r++) {
        ds[r] = acc[r][0] * a0 + acc[r][1] * a1 + acc[r][2] * a2 + acc[r][3] * a3;
        dd[r] = acc[r][0] * b0 + acc[r][1] * b1 + acc[r][2] * b2 + acc[r][3] * b3;
    }
    const int RW = (CH == 64) ? 16 : 8;
    #pragma unroll
    for (int o = RW / 2; o; o >>= 1) {
        #pragma unroll
        for (int r = 0; r < 8; r++) {
            ds[r] += __shfl_down_sync(0xffffffffu, ds[r], o, RW);
            dd[r] += __shfl_down_sync(0xffffffffu, dd[r], o, RW);
        }
    }
    if ((t & (RW - 1)) == 0) {
        #pragma unroll
        for (int r = 0; r < 8; r++) {
            int row = rowBase + ty * 8 + r;
            if (row < NN) {
                es[row * 8 + head] = ds[r];
                ed[row * 8 + head] = dd[r];
            }
        }
    }
}

// ---------------- GCN aggregation (fp16 in) + bias + BN(eval) + ReLU --------
// one warp per dst node; lane owns channel pair (2l, 2l+1).
__global__ __launch_bounds__(256) void gcn_agg_kernel(const __half* __restrict__ h,
                                                      const float* __restrict__ bias,
                                                      const float* __restrict__ gamma,
                                                      const float* __restrict__ beta,
                                                      const float* __restrict__ mean,
                                                      const float* __restrict__ var,
                                                      float* __restrict__ out) {
    int w = (blockIdx.x * blockDim.x + threadIdx.x) >> 5;
    int l = threadIdx.x & 31;
    if (w >= NN) return;
    int s0 = g_rowptr[w], s1 = g_rowptr[w + 1];
    float a0 = 0.f, a1 = 0.f;
    const __half2* hb = (const __half2*)h;
    for (int i = s0; i < s1; i++) {
        int s = g_colsrc[i];
        float dv = g_dinv[s];
        float2 v = __half22float2(hb[s * 32 + l]);
        a0 += dv * v.x;
        a1 += dv * v.y;
    }
    float dd = g_dinv[w];
    float2 bi = ((const float2*)bias)[l];
    float2 me = ((const float2*)mean)[l];
    float2 va = ((const float2*)var)[l];
    float2 ga = ((const float2*)gamma)[l];
    float2 be = ((const float2*)beta)[l];
    float v0 = a0 * dd + bi.x;
    float v1 = a1 * dd + bi.y;
    v0 = (v0 - me.x) * rsqrtf(va.x + BN_EPS) * ga.x + be.x;
    v1 = (v1 - me.y) * rsqrtf(va.y + BN_EPS) * ga.y + be.y;
    ((float2*)(out + (size_t)w * 64))[l] = make_float2(fmaxf(v0, 0.f), fmaxf(v1, 0.f));
}

// ---------------- GAT aggregation: 2 passes (max, then fused den+sum) -------
// one warp per dst. CH=64: lane owns channel pair (2l,2l+1); CH=32: channel l.
template <int CH, int RELU, int LOGSM>
__global__ __launch_bounds__(256) void gat_agg_kernel(const __half* __restrict__ hb,
                                                      const float* __restrict__ es,
                                                      const float* __restrict__ ed,
                                                      const float* __restrict__ bias,
                                                      float* __restrict__ out) {
    int d = (blockIdx.x * blockDim.x + threadIdx.x) >> 5;
    int l = threadIdx.x & 31;
    if (d >= NN) return;
    int s0 = g_rowptr[d], s1 = g_rowptr[d + 1];

    float edv[8];
    {
        const float4* e4 = (const float4*)(ed + d * 8);
        float4 a = e4[0], b = e4[1];
        edv[0] = a.x; edv[1] = a.y; edv[2] = a.z; edv[3] = a.w;
        edv[4] = b.x; edv[5] = b.y; edv[6] = b.z; edv[7] = b.w;
    }

    // pass 1: per-head max (order-independent)
    float m[8];
    #pragma unroll
    for (int h = 0; h < 8; h++) m[h] = -1e30f;
    for (int i = s0 + l; i < s1; i += 32) {
        int s = g_colsrc[i];
        const float4* e4 = (const float4*)(es + s * 8);
        float4 a = e4[0], b = e4[1];
        float ev[8] = {a.x, a.y, a.z, a.w, b.x, b.y, b.z, b.w};
        #pragma unroll
        for (int h = 0; h < 8; h++) m[h] = fmaxf(m[h], lrelu(ev[h] + edv[h]));
    }
    #pragma unroll
    for (int h = 0; h < 8; h++) m[h] = warp_max(m[h]);

    // pass 2 (fused): unnormalized weights + weighted feature sums.
    // Lanes 0..7 compute w for head==lane; den accumulates per-lane (serial
    // edge order -> deterministic). Normalize by den[h] at the end.
    float den = 0.f;
    float acc0[8], acc1[8];
    #pragma unroll
    for (int h = 0; h < 8; h++) { acc0[h] = 0.f; acc1[h] = 0.f; }
    for (int i = s0; i < s1; i++) {
        int s = g_colsrc[i];
        float wv = 0.f;
        if (l < 8) wv = expf(lrelu(es[s * 8 + l] + edv[l]) - m[l]);
        den += wv;
        if (CH == 64) {
            const __half2* hp = (const __half2*)(hb + (size_t)s * 512);
            #pragma unroll
            for (int h = 0; h < 8; h++) {
                float wh = __shfl_sync(0xffffffffu, wv, h);
                float2 v = __half22float2(hp[h * 32 + l]);
                acc0[h] += wh * v.x;
                acc1[h] += wh * v.y;
            }
        } else {
            const __half* hp = hb + (size_t)s * 256;
            #pragma unroll
            for (int h = 0; h < 8; h++) {
                float wh = __shfl_sync(0xffffffffu, wv, h);
                acc0[h] += wh * __half2float(hp[h * 32 + l]);
            }
        }
    }

    float v0 = 0.f, v1 = 0.f;
    #pragma unroll
    for (int h = 0; h < 8; h++) {
        float rd = 1.f / (__shfl_sync(0xffffffffu, den, h) + 1e-16f);
        v0 += acc0[h] * rd;
        if (CH == 64) v1 += acc1[h] * rd;
    }

    if (CH == 64) {
        float2 bi = ((const float2*)bias)[l];
        v0 = v0 * 0.125f + bi.x;
        v1 = v1 * 0.125f + bi.y;
        if (RELU) { v0 = fmaxf(v0, 0.f); v1 = fmaxf(v1, 0.f); }
        ((float2*)(out + (size_t)d * 64))[l] = make_float2(v0, v1);
    } else {
        v0 = v0 * 0.125f + bias[l];
        if (RELU) v0 = fmaxf(v0, 0.f);
        if (LOGSM) {
            float mx = warp_max(v0);
            float se = warp_sum(expf(v0 - mx));
            v0 = v0 - mx - logf(se);
        }
        out[(size_t)d * 32 + l] = v0;
    }
}

// ---------------- launch ----------------
extern "C" void kernel_launch(void* const* d_in, const int* in_sizes, int n_in,
                              void* d_out, int out_size) {
    const float* X        = (const float*)d_in[0];
    const void*  EI       = d_in[1];
    const float* gcn1_w   = (const float*)d_in[2];
    const float* gcn1_b   = (const float*)d_in[3];
    const float* bn1_g    = (const float*)d_in[4];
    const float* bn1_be   = (const float*)d_in[5];
    const float* bn1_m    = (const float*)d_in[6];
    const float* bn1_v    = (const float*)d_in[7];
    const float* gat1_w   = (const float*)d_in[8];
    const float* gat1_as  = (const float*)d_in[9];
    const float* gat1_ad  = (const float*)d_in[10];
    const float* gat1_b   = (const float*)d_in[11];
    const float* gcn2_w   = (const float*)d_in[12];
    const float* gcn2_b   = (const float*)d_in[13];
    const float* bn2_g    = (const float*)d_in[14];
    const float* bn2_be   = (const float*)d_in[15];
    const float* bn2_m    = (const float*)d_in[16];
    const float* bn2_v    = (const float*)d_in[17];
    const float* gat2_w   = (const float*)d_in[18];
    const float* gat2_as  = (const float*)d_in[19];
    const float* gat2_ad  = (const float*)d_in[20];
    const float* gat2_b   = (const float*)d_in[21];
    float* OUT = (float*)d_out;

    float *bufA, *bufB, *es, *ed;
    __half* hbuf;
    int* degPtr;
    cudaGetSymbolAddress((void**)&bufA,   g_bufA);
    cudaGetSymbolAddress((void**)&bufB,   g_bufB);
    cudaGetSymbolAddress((void**)&hbuf,   g_hbuf);
    cudaGetSymbolAddress((void**)&es,     g_es);
    cudaGetSymbolAddress((void**)&ed,     g_ed);
    cudaGetSymbolAddress((void**)&degPtr, g_deg);

    const int TB = 256;
    detect_kernel<<<1, 32>>>((const int*)EI);
    cudaMemsetAsync(degPtr, 0, NN * sizeof(int));
    convert_count_kernel<<<(EE + TB - 1) / TB, TB>>>(EI);
    bsum_kernel<<<NB, 256>>>();
    bscan_kernel<<<1, 256>>>();
    rowptr_kernel<<<NB, 256>>>();
    fill_kernel<<<(E2 + TB - 1) / TB, TB>>>();
    sort_kernel<<<(NN + TB - 1) / TB, TB>>>();

    int gRows     = (NN + 127) / 128;    // 391
    int aggBlocks = (NN * 32 + TB - 1) / TB;

    // layer 1: GCN -> BN -> ReLU   (GEMM writes fp16 for the gather)
    gemm_kernel<128, 64, true><<<dim3(gRows, 1), TB>>>(X, gcn1_w, hbuf);
    gcn_agg_kernel<<<aggBlocks, TB>>>(hbuf, gcn1_b, bn1_g, bn1_be, bn1_m, bn1_v, bufB);

    // layer 2: GAT(8 heads, 64 ch, mean) -> ReLU  [es/ed fused into GEMM]
    gemm_gat_kernel<64, 512, 64><<<dim3(gRows, 8), TB>>>(bufB, gat1_w, gat1_as, gat1_ad, hbuf, es, ed);
    gat_agg_kernel<64, 1, 0><<<aggBlocks, TB>>>(hbuf, es, ed, gat1_b, bufA);

    // layer 3: GCN -> BN -> ReLU
    gemm_kernel<64, 64, true><<<dim3(gRows, 1), TB>>>(bufA, gcn2_w, hbuf);
    gcn_agg_kernel<<<aggBlocks, TB>>>(hbuf, gcn2_b, bn2_g, bn2_be, bn2_m, bn2_v, bufB);

    // layer 4: GAT(8 heads, 32 ch, mean) + log_softmax
    gemm_gat_kernel<64, 256, 32><<<dim3(gRows, 4), TB>>>(bufB, gat2_w, gat2_as, gat2_ad, hbuf, es, ed);
    gat_agg_kernel<32, 0, 1><<<aggBlocks, TB>>>(hbuf, es, ed, gat2_b, OUT);
}

// round 7
// speedup vs baseline: 2.6427x; 1.6821x over previous
#include <cuda_runtime.h>
#include <cuda_fp16.h>
#include <math.h>
#include <stdint.h>

#define NN 50000
#define EE 800000
#define E2 (EE + NN)
#define NB ((NN + 255) / 256)
#define BN_EPS 1e-5f

// ---------------- scratch (static __device__, no allocations) ----------------
__device__ int    g_is64;
__device__ int    g_src[EE];
__device__ int    g_dst[EE];
__device__ int    g_deg[NN];
__device__ int    g_bsum[256];
__device__ int    g_boff[256];
__device__ int    g_rowptr[NN + 1];
__device__ int    g_fill[NN];
__device__ int    g_colsrc[E2];
__device__ float  g_dinv[NN];
__device__ float  g_bufA[NN * 64];
__device__ float  g_bufB[NN * 64];
__device__ __half g_hbuf[(size_t)NN * 512];   // 51.2 MB fp16 feature buffer
__device__ float  g_es[NN * 8];
__device__ float  g_ed[NN * 8];

// ---------------- helpers ----------------
__device__ __forceinline__ float warp_max(float v) {
    #pragma unroll
    for (int o = 16; o; o >>= 1) v = fmaxf(v, __shfl_xor_sync(0xffffffffu, v, o));
    return v;
}
__device__ __forceinline__ float warp_sum(float v) {
    #pragma unroll
    for (int o = 16; o; o >>= 1) v += __shfl_xor_sync(0xffffffffu, v, o);
    return v;
}
__device__ __forceinline__ float lrelu(float x) { return x > 0.f ? x : 0.2f * x; }

// ---------------- graph-structure kernels ----------------
__global__ void detect_kernel(const int* __restrict__ ei) {
    int l = threadIdx.x;
    int any = 0;
    #pragma unroll
    for (int j = 0; j < 32; j++) any |= ei[2 * (j * 32 + l) + 1];
    #pragma unroll
    for (int o = 16; o; o >>= 1) any |= __shfl_xor_sync(0xffffffffu, any, o);
    if (l == 0) g_is64 = (any == 0) ? 1 : 0;
}

__global__ void convert_count_kernel(const void* __restrict__ ei) {
    int e = blockIdx.x * blockDim.x + threadIdx.x;
    if (e >= EE) return;
    int s, d;
    if (g_is64) {
        const long long* p = (const long long*)ei;
        s = (int)p[e];
        d = (int)p[EE + e];
    } else {
        const int* p = (const int*)ei;
        s = p[e];
        d = p[EE + e];
    }
    g_src[e] = s;
    g_dst[e] = d;
    atomicAdd(&g_deg[d], 1);
}

__global__ __launch_bounds__(256) void bsum_kernel() {
    __shared__ int sh[256];
    int t = threadIdx.x;
    int n = blockIdx.x * 256 + t;
    int v = (n < NN) ? (g_deg[n] + 1) : 0;
    sh[t] = v;
    __syncthreads();
    #pragma unroll
    for (int o = 128; o; o >>= 1) {
        if (t < o) sh[t] += sh[t + o];
        __syncthreads();
    }
    if (t == 0) g_bsum[blockIdx.x] = sh[0];
}

__global__ __launch_bounds__(256) void bscan_kernel() {
    __shared__ int sh[256];
    int t = threadIdx.x;
    int v = (t < NB) ? g_bsum[t] : 0;
    sh[t] = v;
    __syncthreads();
    #pragma unroll
    for (int o = 1; o < 256; o <<= 1) {
        int u = (t >= o) ? sh[t - o] : 0;
        __syncthreads();
        sh[t] += u;
        __syncthreads();
    }
    g_boff[t] = sh[t] - v;
}

__global__ __launch_bounds__(256) void rowptr_kernel() {
    __shared__ int sh[256];
    int t = threadIdx.x;
    int n = blockIdx.x * 256 + t;
    int v = (n < NN) ? (g_deg[n] + 1) : 0;
    sh[t] = v;
    __syncthreads();
    #pragma unroll
    for (int o = 1; o < 256; o <<= 1) {
        int u = (t >= o) ? sh[t - o] : 0;
        __syncthreads();
        sh[t] += u;
        __syncthreads();
    }
    int excl = sh[t] - v + g_boff[blockIdx.x];
    if (n < NN) {
        g_rowptr[n] = excl;
        g_fill[n]   = excl;
        g_dinv[n]   = rsqrtf((float)v);
    }
    if (n == NN - 1) g_rowptr[NN] = excl + v;
}

__global__ void fill_kernel() {
    int idx = blockIdx.x * blockDim.x + threadIdx.x;
    if (idx >= E2) return;
    int s, d;
    if (idx < EE) { s = g_src[idx]; d = g_dst[idx]; }
    else          { s = d = idx - EE; }
    int pos = atomicAdd(&g_fill[d], 1);
    g_colsrc[pos] = s;
}

__global__ void sort_kernel() {
    int r = blockIdx.x * blockDim.x + threadIdx.x;
    if (r >= NN) return;
    int s0 = g_rowptr[r], s1 = g_rowptr[r + 1];
    for (int i = s0 + 1; i < s1; i++) {
        int v = g_colsrc[i];
        int j = i - 1;
        while (j >= s0 && g_colsrc[j] > v) { g_colsrc[j + 1] = g_colsrc[j]; j--; }
        g_colsrc[j + 1] = v;
    }
}

// ---------------- tensor-core GEMM: Y(fp16)[M,NO] = X(fp32)[M,K] @ W[K,NO] ---
// 128x64 block tile, 256 threads = 8 warps (4 row-groups x 2 col-groups),
// each warp 32x32 via mma.sync.m16n8k16 (fp16 in, fp32 accum).
// smem strides padded to 72 halves = 144 B (144 % 128 = 16 -> LDSM conflict-free).
template <int K, int NO>
__global__ __launch_bounds__(256) void tc_gemm_kernel(const float* __restrict__ X,
                                                      const float* __restrict__ W,
                                                      __half* __restrict__ Y) {
    __shared__ __half As[128][72];
    __shared__ __half Bs[64][72];
    int t = threadIdx.x;
    int lane = t & 31, wid = t >> 5;
    int warp_m = wid & 3, warp_n = wid >> 2;
    int rowBase = blockIdx.x * 128;
    int colBase = blockIdx.y * 64;

    float c[2][4][4];
    #pragma unroll
    for (int mt = 0; mt < 2; mt++)
        #pragma unroll
        for (int nt = 0; nt < 4; nt++)
            #pragma unroll
            for (int i = 0; i < 4; i++) c[mt][nt][i] = 0.f;

    for (int kc = 0; kc < K; kc += 64) {
        if (kc) __syncthreads();
        // stage A (fp32 -> fp16), 128 rows x 64 halves
        #pragma unroll
        for (int i = 0; i < 8; i++) {
            int idx = i * 256 + t;
            int r = idx >> 4, g = idx & 15;
            int row = rowBase + r;
            float4 f = (row < NN)
                ? *(const float4*)(X + (size_t)row * K + kc + g * 4)
                : make_float4(0.f, 0.f, 0.f, 0.f);
            *(__half2*)&As[r][g * 4]     = __floats2half2_rn(f.x, f.y);
            *(__half2*)&As[r][g * 4 + 2] = __floats2half2_rn(f.z, f.w);
        }
        // stage B, 64 k x 64 cols
        #pragma unroll
        for (int i = 0; i < 4; i++) {
            int idx = i * 256 + t;
            int k = idx >> 4, g = idx & 15;
            float4 f = *(const float4*)(W + (size_t)(kc + k) * NO + colBase + g * 4);
            *(__half2*)&Bs[k][g * 4]     = __floats2half2_rn(f.x, f.y);
            *(__half2*)&Bs[k][g * 4 + 2] = __floats2half2_rn(f.z, f.w);
        }
        __syncthreads();
        #pragma unroll
        for (int ks = 0; ks < 4; ks++) {
            uint32_t a[2][4], b[2][4];
            #pragma unroll
            for (int mt = 0; mt < 2; mt++) {
                const __half* p = &As[warp_m * 32 + mt * 16 + (lane & 15)][ks * 16 + (lane >> 4) * 8];
                uint32_t addr = (uint32_t)__cvta_generic_to_shared(p);
                asm volatile("ldmatrix.sync.aligned.m8n8.x4.shared.b16 {%0,%1,%2,%3}, [%4];"
                    : "=r"(a[mt][0]), "=r"(a[mt][1]), "=r"(a[mt][2]), "=r"(a[mt][3])
                    : "r"(addr));
            }
            #pragma unroll
            for (int ng = 0; ng < 2; ng++) {
                const __half* p = &Bs[ks * 16 + (lane & 15)][warp_n * 32 + ng * 16 + (lane >> 4) * 8];
                uint32_t addr = (uint32_t)__cvta_generic_to_shared(p);
                asm volatile("ldmatrix.sync.aligned.m8n8.x4.trans.shared.b16 {%0,%1,%2,%3}, [%4];"
                    : "=r"(b[ng][0]), "=r"(b[ng][1]), "=r"(b[ng][2]), "=r"(b[ng][3])
                    : "r"(addr));
            }
            #pragma unroll
            for (int mt = 0; mt < 2; mt++)
                #pragma unroll
                for (int nt = 0; nt < 4; nt++) {
                    uint32_t b0 = b[nt >> 1][(nt & 1) * 2];
                    uint32_t b1 = b[nt >> 1][(nt & 1) * 2 + 1];
                    asm volatile(
                        "mma.sync.aligned.m16n8k16.row.col.f32.f16.f16.f32 "
                        "{%0,%1,%2,%3}, {%4,%5,%6,%7}, {%8,%9}, {%0,%1,%2,%3};"
                        : "+f"(c[mt][nt][0]), "+f"(c[mt][nt][1]),
                          "+f"(c[mt][nt][2]), "+f"(c[mt][nt][3])
                        : "r"(a[mt][0]), "r"(a[mt][1]), "r"(a[mt][2]), "r"(a[mt][3]),
                          "r"(b0), "r"(b1));
                }
        }
    }
    // store fp16
    #pragma unroll
    for (int mt = 0; mt < 2; mt++) {
        int r0 = rowBase + warp_m * 32 + mt * 16 + (lane >> 2);
        #pragma unroll
        for (int nt = 0; nt < 4; nt++) {
            int col = colBase + warp_n * 32 + nt * 8 + (lane & 3) * 2;
            if (r0 < NN)
                *(__half2*)(Y + (size_t)r0 * NO + col) = __floats2half2_rn(c[mt][nt][0], c[mt][nt][1]);
            if (r0 + 8 < NN)
                *(__half2*)(Y + (size_t)(r0 + 8) * NO + col) = __floats2half2_rn(c[mt][nt][2], c[mt][nt][3]);
        }
    }
}

// ---------------- GAT attention coefficients from fp16 features -------------
// one warp per (node, head).
template <int CH>
__global__ __launch_bounds__(256) void esed_kernel(const __half* __restrict__ hb,
                                                   const float* __restrict__ asrc,
                                                   const float* __restrict__ adst,
                                                   float* __restrict__ es,
                                                   float* __restrict__ ed) {
    int wid = (blockIdx.x * blockDim.x + threadIdx.x) >> 5;
    int l   = threadIdx.x & 31;
    if (wid >= NN * 8) return;
    int n = wid >> 3, hh = wid & 7;
    const __half* hp = hb + (size_t)n * (8 * CH) + hh * CH;
    const float* as = asrc + hh * CH;
    const float* ad = adst + hh * CH;
    float s, d;
    if (CH == 64) {
        float2 v = __half22float2(*(const __half2*)(hp + 2 * l));
        s = v.x * as[2 * l] + v.y * as[2 * l + 1];
        d = v.x * ad[2 * l] + v.y * ad[2 * l + 1];
    } else {
        float v = __half2float(hp[l]);
        s = v * as[l];
        d = v * ad[l];
    }
    s = warp_sum(s);
    d = warp_sum(d);
    if (l == 0) { es[n * 8 + hh] = s; ed[n * 8 + hh] = d; }
}

// ---------------- GCN aggregation (fp16 in) + bias + BN(eval) + ReLU --------
__global__ __launch_bounds__(256) void gcn_agg_kernel(const __half* __restrict__ h,
                                                      const float* __restrict__ bias,
                                                      const float* __restrict__ gamma,
                                                      const float* __restrict__ beta,
                                                      const float* __restrict__ mean,
                                                      const float* __restrict__ var,
                                                      float* __restrict__ out) {
    int w = (blockIdx.x * blockDim.x + threadIdx.x) >> 5;
    int l = threadIdx.x & 31;
    if (w >= NN) return;
    int s0 = g_rowptr[w], s1 = g_rowptr[w + 1];
    float a0 = 0.f, a1 = 0.f;
    const __half2* hb = (const __half2*)h;
    for (int i = s0; i < s1; i++) {
        int s = g_colsrc[i];
        float dv = g_dinv[s];
        float2 v = __half22float2(hb[s * 32 + l]);
        a0 += dv * v.x;
        a1 += dv * v.y;
    }
    float dd = g_dinv[w];
    float2 bi = ((const float2*)bias)[l];
    float2 me = ((const float2*)mean)[l];
    float2 va = ((const float2*)var)[l];
    float2 ga = ((const float2*)gamma)[l];
    float2 be = ((const float2*)beta)[l];
    float v0 = a0 * dd + bi.x;
    float v1 = a1 * dd + bi.y;
    v0 = (v0 - me.x) * rsqrtf(va.x + BN_EPS) * ga.x + be.x;
    v1 = (v1 - me.y) * rsqrtf(va.y + BN_EPS) * ga.y + be.y;
    ((float2*)(out + (size_t)w * 64))[l] = make_float2(fmaxf(v0, 0.f), fmaxf(v1, 0.f));
}

// ---------------- GAT aggregation: max pass + fused den/sum pass ------------
template <int CH, int RELU, int LOGSM>
__global__ __launch_bounds__(256) void gat_agg_kernel(const __half* __restrict__ hb,
                                                      const float* __restrict__ es,
                                                      const float* __restrict__ ed,
                                                      const float* __restrict__ bias,
                                                      float* __restrict__ out) {
    int d = (blockIdx.x * blockDim.x + threadIdx.x) >> 5;
    int l = threadIdx.x & 31;
    if (d >= NN) return;
    int s0 = g_rowptr[d], s1 = g_rowptr[d + 1];

    float edv[8];
    {
        const float4* e4 = (const float4*)(ed + d * 8);
        float4 a = e4[0], b = e4[1];
        edv[0] = a.x; edv[1] = a.y; edv[2] = a.z; edv[3] = a.w;
        edv[4] = b.x; edv[5] = b.y; edv[6] = b.z; edv[7] = b.w;
    }

    // pass 1: per-head max
    float m[8];
    #pragma unroll
    for (int h = 0; h < 8; h++) m[h] = -1e30f;
    for (int i = s0 + l; i < s1; i += 32) {
        int s = g_colsrc[i];
        const float4* e4 = (const float4*)(es + s * 8);
        float4 a = e4[0], b = e4[1];
        float ev[8] = {a.x, a.y, a.z, a.w, b.x, b.y, b.z, b.w};
        #pragma unroll
        for (int h = 0; h < 8; h++) m[h] = fmaxf(m[h], lrelu(ev[h] + edv[h]));
    }
    #pragma unroll
    for (int h = 0; h < 8; h++) m[h] = warp_max(m[h]);

    // pass 2 (fused): unnormalized weights + weighted feature sums.
    float den = 0.f;
    float acc0[8], acc1[8];
    #pragma unroll
    for (int h = 0; h < 8; h++) { acc0[h] = 0.f; acc1[h] = 0.f; }
    for (int i = s0; i < s1; i++) {
        int s = g_colsrc[i];
        float wv = 0.f;
        if (l < 8) wv = expf(lrelu(es[s * 8 + l] + edv[l]) - m[l]);
        den += wv;
        if (CH == 64) {
            const __half2* hp = (const __half2*)(hb + (size_t)s * 512);
            #pragma unroll
            for (int h = 0; h < 8; h++) {
                float wh = __shfl_sync(0xffffffffu, wv, h);
                float2 v = __half22float2(hp[h * 32 + l]);
                acc0[h] += wh * v.x;
                acc1[h] += wh * v.y;
            }
        } else {
            const __half* hp = hb + (size_t)s * 256;
            #pragma unroll
            for (int h = 0; h < 8; h++) {
                float wh = __shfl_sync(0xffffffffu, wv, h);
                acc0[h] += wh * __half2float(hp[h * 32 + l]);
            }
        }
    }

    float v0 = 0.f, v1 = 0.f;
    #pragma unroll
    for (int h = 0; h < 8; h++) {
        float rd = 1.f / (__shfl_sync(0xffffffffu, den, h) + 1e-16f);
        v0 += acc0[h] * rd;
        if (CH == 64) v1 += acc1[h] * rd;
    }

    if (CH == 64) {
        float2 bi = ((const float2*)bias)[l];
        v0 = v0 * 0.125f + bi.x;
        v1 = v1 * 0.125f + bi.y;
        if (RELU) { v0 = fmaxf(v0, 0.f); v1 = fmaxf(v1, 0.f); }
        ((float2*)(out + (size_t)d * 64))[l] = make_float2(v0, v1);
    } else {
        v0 = v0 * 0.125f + bias[l];
        if (RELU) v0 = fmaxf(v0, 0.f);
        if (LOGSM) {
            float mx = warp_max(v0);
            float se = warp_sum(expf(v0 - mx));
            v0 = v0 - mx - logf(se);
        }
        out[(size_t)d * 32 + l] = v0;
    }
}

// ---------------- launch ----------------
extern "C" void kernel_launch(void* const* d_in, const int* in_sizes, int n_in,
                              void* d_out, int out_size) {
    const float* X        = (const float*)d_in[0];
    const void*  EI       = d_in[1];
    const float* gcn1_w   = (const float*)d_in[2];
    const float* gcn1_b   = (const float*)d_in[3];
    const float* bn1_g    = (const float*)d_in[4];
    const float* bn1_be   = (const float*)d_in[5];
    const float* bn1_m    = (const float*)d_in[6];
    const float* bn1_v    = (const float*)d_in[7];
    const float* gat1_w   = (const float*)d_in[8];
    const float* gat1_as  = (const float*)d_in[9];
    const float* gat1_ad  = (const float*)d_in[10];
    const float* gat1_b   = (const float*)d_in[11];
    const float* gcn2_w   = (const float*)d_in[12];
    const float* gcn2_b   = (const float*)d_in[13];
    const float* bn2_g    = (const float*)d_in[14];
    const float* bn2_be   = (const float*)d_in[15];
    const float* bn2_m    = (const float*)d_in[16];
    const float* bn2_v    = (const float*)d_in[17];
    const float* gat2_w   = (const float*)d_in[18];
    const float* gat2_as  = (const float*)d_in[19];
    const float* gat2_ad  = (const float*)d_in[20];
    const float* gat2_b   = (const float*)d_in[21];
    float* OUT = (float*)d_out;

    float *bufA, *bufB, *es, *ed;
    __half* hbuf;
    int* degPtr;
    cudaGetSymbolAddress((void**)&bufA,   g_bufA);
    cudaGetSymbolAddress((void**)&bufB,   g_bufB);
    cudaGetSymbolAddress((void**)&hbuf,   g_hbuf);
    cudaGetSymbolAddress((void**)&es,     g_es);
    cudaGetSymbolAddress((void**)&ed,     g_ed);
    cudaGetSymbolAddress((void**)&degPtr, g_deg);

    const int TB = 256;
    detect_kernel<<<1, 32>>>((const int*)EI);
    cudaMemsetAsync(degPtr, 0, NN * sizeof(int));
    convert_count_kernel<<<(EE + TB - 1) / TB, TB>>>(EI);
    bsum_kernel<<<NB, 256>>>();
    bscan_kernel<<<1, 256>>>();
    rowptr_kernel<<<NB, 256>>>();
    fill_kernel<<<(E2 + TB - 1) / TB, TB>>>();
    sort_kernel<<<(NN + TB - 1) / TB, TB>>>();

    int gRows      = (NN + 127) / 128;   // 391
    int aggBlocks  = (NN * 32 + TB - 1) / TB;
    int esedBlocks = (NN * 8 * 32 + TB - 1) / TB;

    // layer 1: GCN -> BN -> ReLU
    tc_gemm_kernel<128, 64><<<dim3(gRows, 1), TB>>>(X, gcn1_w, hbuf);
    gcn_agg_kernel<<<aggBlocks, TB>>>(hbuf, gcn1_b, bn1_g, bn1_be, bn1_m, bn1_v, bufB);

    // layer 2: GAT(8 heads, 64 ch, mean) -> ReLU
    tc_gemm_kernel<64, 512><<<dim3(gRows, 8), TB>>>(bufB, gat1_w, hbuf);
    esed_kernel<64><<<esedBlocks, TB>>>(hbuf, gat1_as, gat1_ad, es, ed);
    gat_agg_kernel<64, 1, 0><<<aggBlocks, TB>>>(hbuf, es, ed, gat1_b, bufA);

    // layer 3: GCN -> BN -> ReLU
    tc_gemm_kernel<64, 64><<<dim3(gRows, 1), TB>>>(bufA, gcn2_w, hbuf);
    gcn_agg_kernel<<<aggBlocks, TB>>>(hbuf, gcn2_b, bn2_g, bn2_be, bn2_m, bn2_v, bufB);

    // layer 4: GAT(8 heads, 32 ch, mean) + log_softmax
    tc_gemm_kernel<64, 256><<<dim3(gRows, 4), TB>>>(bufB, gat2_w, hbuf);
    esed_kernel<32><<<esedBlocks, TB>>>(hbuf, gat2_as, gat2_ad, es, ed);
    gat_agg_kernel<32, 0, 1><<<aggBlocks, TB>>>(hbuf, es, ed, gat2_b, OUT);
}